// round 2
// baseline (speedup 1.0000x reference)
#include <cuda_runtime.h>
#include <math.h>

#define D 128
#define C 10
#define NMAX 4096
#define BM 128
#define BN 128
#define BK 32

// -------- device scratch (no allocations allowed) --------
__device__ double g_Sacc[32];          // [class*3 + {S0,S1,S2}]
__device__ int    g_counts[C];
__device__ float  g_invCnt[C];
__device__ float  g_invwn[C];
__device__ float  g_exist;
__device__ float  g_sq[NMAX];
__device__ float  g_proj[NMAX * C];
__device__ int    g_cls[NMAX];
__device__ float  g_pcl[NMAX];         // proj[r][cls[r]]
__device__ float  g_invwnCls[NMAX];    // 1/wn[cls[r]]
__device__ float  g_invC[NMAX];        // 1/counts[cls[r]]

__device__ __forceinline__ int clampC(int v) {
    return v < 0 ? 0 : (v >= C ? C - 1 : v);
}

// ---------------- prep1: counts, wn, exist, zero accumulators ----------------
__global__ void prep1(const int* __restrict__ target,
                      const float* __restrict__ W, int N)
{
    __shared__ int cnt[C];
    int tid = threadIdx.x;
    if (tid < 32) g_Sacc[tid] = 0.0;
    if (tid < C)  cnt[tid] = 0;
    __syncthreads();
    for (int i = tid; i < N; i += blockDim.x) {
        atomicAdd(&cnt[clampC(target[i])], 1);
    }
    __syncthreads();
    if (tid < C) {
        int cc = cnt[tid];
        g_counts[tid] = cc;
        g_invCnt[tid] = 1.0f / (float)max(cc, 1);
        float s = 0.f;
        #pragma unroll 8
        for (int k = 0; k < D; k++) { float w = W[tid * D + k]; s = fmaf(w, w, s); }
        float wn = fmaxf(sqrtf(s), 1e-8f);
        g_invwn[tid] = 1.0f / wn;
    }
    __syncthreads();
    if (tid == 0) {
        int e = 0;
        for (int c = 0; c < C; c++) e += (cnt[c] > 0);
        g_exist = (float)e;
    }
}

// ---------------- prep2: per-row sq, proj[10], derived per-row scalars -------
__global__ void prep2(const float* __restrict__ pred,
                      const int* __restrict__ target,
                      const float* __restrict__ W, int N)
{
    __shared__ float Wsh[C][D];
    int tid = threadIdx.x;
    for (int i = tid; i < C * D; i += blockDim.x) Wsh[i / D][i % D] = W[i];
    __syncthreads();
    int r = blockIdx.x * blockDim.x + tid;
    if (r >= N) return;

    const float4* p4 = (const float4*)(pred + (size_t)r * D);
    float sq = 0.f;
    float proj[C];
    #pragma unroll
    for (int c = 0; c < C; c++) proj[c] = 0.f;

    #pragma unroll 4
    for (int q = 0; q < D / 4; q++) {
        float4 v = p4[q];
        float vv[4] = {v.x, v.y, v.z, v.w};
        #pragma unroll
        for (int j = 0; j < 4; j++) {
            float p = vv[j];
            int k = q * 4 + j;
            sq = fmaf(p, p, sq);
            #pragma unroll
            for (int c = 0; c < C; c++) proj[c] = fmaf(p, Wsh[c][k], proj[c]);
        }
    }
    g_sq[r] = sq;
    int cl = clampC(target[r]);
    g_cls[r] = cl;
    #pragma unroll
    for (int c = 0; c < C; c++) g_proj[(size_t)r * C + c] = proj[c];
    g_pcl[r]      = proj[cl];
    g_invwnCls[r] = g_invwn[cl];
    g_invC[r]     = g_invCnt[cl];
}

// ---------------- main: fused pairwise GEMM + loss epilogue ------------------
__global__ __launch_bounds__(256, 2)
void pairKernel(const float* __restrict__ pred, int N)
{
    __shared__ float As[BK][BM];       // K-major A tile (transposed on load)
    __shared__ float Bs[BK][BN];
    __shared__ float projB[C][BN];     // class-major proj of b-columns
    __shared__ float aSq[BM], aP[BM], aIW[BM], aIC[BM];
    __shared__ float bSq[BN], bIC[BN];
    __shared__ int   aCl[BM], bCl[BN];
    __shared__ double sacc[C * 3];

    int tid   = threadIdx.x;
    int aBase = blockIdx.y * BM;
    int bBase = blockIdx.x * BN;

    if (tid < C * 3) sacc[tid] = 0.0;
    if (tid < BM) {
        int ga = aBase + tid;
        aSq[tid] = g_sq[ga];  aP[tid]  = g_pcl[ga];
        aIW[tid] = g_invwnCls[ga]; aIC[tid] = g_invC[ga]; aCl[tid] = g_cls[ga];
        int gb = bBase + tid;
        bSq[tid] = g_sq[gb];  bIC[tid] = g_invC[gb]; bCl[tid] = g_cls[gb];
    }
    for (int i = tid; i < C * BN; i += 256) {
        int c = i / BN, b = i % BN;
        projB[c][b] = g_proj[(size_t)(bBase + b) * C + c];
    }

    int tx = tid & 15, ty = tid >> 4;

    float acc[8][8];
    #pragma unroll
    for (int i = 0; i < 8; i++)
        #pragma unroll
        for (int j = 0; j < 8; j++) acc[i][j] = 0.f;

    for (int kb = 0; kb < D; kb += BK) {
        __syncthreads();
        #pragma unroll
        for (int m = 0; m < 4; m++) {
            int lid  = tid + m * 256;
            int row  = lid >> 3;      // 0..127
            int quad = lid & 7;       // 0..7 -> k offset quad*4
            float4 va = *(const float4*)&pred[(size_t)(aBase + row) * D + kb + quad * 4];
            As[quad * 4 + 0][row] = va.x; As[quad * 4 + 1][row] = va.y;
            As[quad * 4 + 2][row] = va.z; As[quad * 4 + 3][row] = va.w;
            float4 vb = *(const float4*)&pred[(size_t)(bBase + row) * D + kb + quad * 4];
            Bs[quad * 4 + 0][row] = vb.x; Bs[quad * 4 + 1][row] = vb.y;
            Bs[quad * 4 + 2][row] = vb.z; Bs[quad * 4 + 3][row] = vb.w;
        }
        __syncthreads();
        #pragma unroll
        for (int k = 0; k < BK; k++) {
            float4 a0 = *(const float4*)&As[k][ty * 4];
            float4 a1 = *(const float4*)&As[k][ty * 4 + 64];
            float4 b0 = *(const float4*)&Bs[k][tx * 4];
            float4 b1 = *(const float4*)&Bs[k][tx * 4 + 64];
            float af[8] = {a0.x, a0.y, a0.z, a0.w, a1.x, a1.y, a1.z, a1.w};
            float bf[8] = {b0.x, b0.y, b0.z, b0.w, b1.x, b1.y, b1.z, b1.w};
            #pragma unroll
            for (int i = 0; i < 8; i++)
                #pragma unroll
                for (int j = 0; j < 8; j++)
                    acc[i][j] = fmaf(af[i], bf[j], acc[i][j]);
        }
    }

    // -------- epilogue: per-pair loss terms -> per-class (S0,S1,S2) --------
    float s0[8], s1[8], s2[8];
    #pragma unroll
    for (int i = 0; i < 8; i++) { s0[i] = 0.f; s1[i] = 0.f; s2[i] = 0.f; }

    #pragma unroll
    for (int i = 0; i < 8; i++) {
        int r = ty * 4 + (i & 3) + (i >> 2) * 64;
        int   ca  = aCl[r];
        float pa  = aP[r], iw = aIW[r], ica = aIC[r], sqa = aSq[r];
        #pragma unroll
        for (int j = 0; j < 8; j++) {
            int c = tx * 4 + (j & 3) + (j >> 2) * 64;
            float g  = acc[i][j];
            float d2 = fmaxf(sqa + bSq[c] - 2.0f * g, 0.0f) + 1e-16f;
            float invdn = rsqrtf(d2);        // dn = max(sqrt(d2+1e-16), 1e-8) == sqrt(d2+1e-16)
            if (bCl[c] != ca) {              // also excludes a==b
                float M = (pa - projB[ca][c]) * iw * invdn;
                float w = ica * bIC[c];
                s0[i] += w;
                s1[i] = fmaf(w, M, s1[i]);
                s2[i] = fmaf(w * M, M, s2[i]);
            }
        }
    }

    #pragma unroll
    for (int i = 0; i < 8; i++) {
        int r  = ty * 4 + (i & 3) + (i >> 2) * 64;
        int ca = aCl[r];
        atomicAdd(&sacc[ca * 3 + 0], (double)s0[i]);
        atomicAdd(&sacc[ca * 3 + 1], (double)s1[i]);
        atomicAdd(&sacc[ca * 3 + 2], (double)s2[i]);
    }
    __syncthreads();
    if (tid < C * 3) atomicAdd(&g_Sacc[tid], sacc[tid]);
}

// ---------------- finalize ----------------
__global__ void finalize(float* __restrict__ out)
{
    double e   = (double)g_exist;
    double inv = 1.0 / (e - 1.0);
    double l1 = 0.0, l2 = 0.0;
    for (int c = 0; c < C; c++) {
        if (g_counts[c] > 0) {
            double S0 = g_Sacc[c * 3 + 0];
            double S1 = g_Sacc[c * 3 + 1];
            double S2 = g_Sacc[c * 3 + 2];
            l1 += (S0 - 2.0 * S1 + S2) * inv;
            double mm = S1 * inv;
            double mv = (S2 - 2.0 * mm * S1 + mm * mm * S0) * inv;
            l2 += fabs(mv / mm);
        }
    }
    out[0] = (float)(l1 / e);
    out[1] = (float)(l2 / e);
}

// ---------------- launch ----------------
extern "C" void kernel_launch(void* const* d_in, const int* in_sizes, int n_in,
                              void* d_out, int out_size)
{
    const float* pred   = (const float*)d_in[0];
    const int*   target = (const int*)d_in[1];      // JAX x64-disabled: int64 -> int32
    const float* W      = (const float*)d_in[2];
    int N = in_sizes[0] / D;   // 4096

    prep1<<<1, 256>>>(target, W, N);
    prep2<<<(N + 127) / 128, 128>>>(pred, target, W, N);
    dim3 grid(N / BN, N / BM);
    pairKernel<<<grid, 256>>>(pred, N);
    finalize<<<1, 1>>>((float*)d_out);
}

// round 3
// speedup vs baseline: 3.2899x; 3.2899x over previous
#include <cuda_runtime.h>
#include <math.h>

#define D 128
#define C 10
#define NMAX 4096
#define BM 128
#define BN 128
#define BK 32

typedef unsigned long long ull;

// -------- device scratch --------
__device__ double g_Sacc[32];          // [class*3 + {S0,S1,S2}]
__device__ int    g_counts[C];
__device__ float  g_invCnt[C];
__device__ float  g_invwn[C];
__device__ float  g_exist;
__device__ float  g_sq[NMAX];
__device__ float  g_proj[NMAX * C];
__device__ int    g_cls[NMAX];
__device__ float  g_pcl[NMAX];         // proj[r][cls[r]]
__device__ float  g_invwnCls[NMAX];    // 1/wn[cls[r]]
__device__ float  g_invC[NMAX];        // 1/counts[cls[r]]
__device__ unsigned int g_done = 0;

__device__ __forceinline__ int clampC(int v) { return v < 0 ? 0 : (v >= C ? C - 1 : v); }

__device__ __forceinline__ ull pack2(float x, float y) {
    ull r; asm("mov.b64 %0, {%1,%2};" : "=l"(r) : "f"(x), "f"(y)); return r;
}
__device__ __forceinline__ void fma2(ull& d, ull a, ull b) {
    asm("fma.rn.f32x2 %0, %1, %2, %0;" : "+l"(d) : "l"(a), "l"(b));
}
__device__ __forceinline__ float2 unpack2(ull v) {
    float2 f; asm("mov.b64 {%0,%1}, %2;" : "=f"(f.x), "=f"(f.y) : "l"(v)); return f;
}

// ---------------- prep1 ----------------
__global__ void prep1(const int* __restrict__ target,
                      const float* __restrict__ W, int N)
{
    __shared__ int cnt[C];
    int tid = threadIdx.x;
    if (tid < 32) g_Sacc[tid] = 0.0;
    if (tid < C)  cnt[tid] = 0;
    __syncthreads();
    for (int i = tid; i < N; i += blockDim.x)
        atomicAdd(&cnt[clampC(target[i])], 1);
    __syncthreads();
    if (tid < C) {
        int cc = cnt[tid];
        g_counts[tid] = cc;
        g_invCnt[tid] = 1.0f / (float)max(cc, 1);
        float s = 0.f;
        #pragma unroll 8
        for (int k = 0; k < D; k++) { float w = W[tid * D + k]; s = fmaf(w, w, s); }
        g_invwn[tid] = 1.0f / fmaxf(sqrtf(s), 1e-8f);
    }
    __syncthreads();
    if (tid == 0) {
        int e = 0;
        for (int c = 0; c < C; c++) e += (cnt[c] > 0);
        g_exist = (float)e;
    }
}

// ---------------- prep2 ----------------
__global__ void prep2(const float* __restrict__ pred,
                      const int* __restrict__ target,
                      const float* __restrict__ W, int N)
{
    __shared__ float Wsh[C][D];
    int tid = threadIdx.x;
    for (int i = tid; i < C * D; i += blockDim.x) Wsh[i / D][i % D] = W[i];
    __syncthreads();
    int r = blockIdx.x * blockDim.x + tid;
    if (r >= N) return;

    const float4* p4 = (const float4*)(pred + (size_t)r * D);
    float sq = 0.f;
    float proj[C];
    #pragma unroll
    for (int c = 0; c < C; c++) proj[c] = 0.f;
    #pragma unroll 4
    for (int q = 0; q < D / 4; q++) {
        float4 v = p4[q];
        float vv[4] = {v.x, v.y, v.z, v.w};
        #pragma unroll
        for (int j = 0; j < 4; j++) {
            float p = vv[j];
            int k = q * 4 + j;
            sq = fmaf(p, p, sq);
            #pragma unroll
            for (int c = 0; c < C; c++) proj[c] = fmaf(p, Wsh[c][k], proj[c]);
        }
    }
    g_sq[r] = sq;
    int cl = clampC(target[r]);
    g_cls[r] = cl;
    #pragma unroll
    for (int c = 0; c < C; c++) g_proj[(size_t)r * C + c] = proj[c];
    g_pcl[r]      = proj[cl];
    g_invwnCls[r] = g_invwn[cl];
    g_invC[r]     = g_invCnt[cl];
}

// ---------------- main: triangular fused pairwise GEMM + loss epilogue ------
__global__ __launch_bounds__(256, 2)
void pairKernel(const float* __restrict__ pred, float* __restrict__ out, int nb)
{
    __shared__ __align__(16) float As[BK][BM];
    __shared__ __align__(16) float Bs[BK][BN];
    __shared__ float projA[C][BM];
    __shared__ float projB[C][BN];
    __shared__ float aSq[BM], aP[BM], aIW[BM], aIC[BM];
    __shared__ float bSq[BN], bP[BN], bIW[BN], bIC[BN];
    __shared__ int   aCl[BM], bCl[BN];
    __shared__ float rA0[BM], rA1[BM], rA2[BM];
    __shared__ float tB0[BN], tB1[BN], tB2[BN];
    __shared__ double sacc[32];

    int tid = threadIdx.x;
    int idx = blockIdx.x;
    // triangular decode: row bi (<= bj)
    int bi = (int)(((float)(2 * nb + 1)
             - sqrtf((float)((2 * nb + 1) * (2 * nb + 1) - 8 * idx))) * 0.5f);
    while ((bi + 1) * nb - ((bi + 1) * bi) / 2 <= idx) bi++;
    while (bi * nb - (bi * (bi - 1)) / 2 > idx) bi--;
    int bj = bi + (idx - (bi * nb - (bi * (bi - 1)) / 2));
    int aBase = bi * BM, bBase = bj * BN;
    bool offd = (bi != bj);

    if (tid < 32) sacc[tid] = 0.0;
    if (tid < BM) {
        int ga = aBase + tid, gb = bBase + tid;
        aSq[tid] = g_sq[ga]; aP[tid] = g_pcl[ga]; aIW[tid] = g_invwnCls[ga];
        aIC[tid] = g_invC[ga]; aCl[tid] = g_cls[ga];
        bSq[tid] = g_sq[gb]; bP[tid] = g_pcl[gb]; bIW[tid] = g_invwnCls[gb];
        bIC[tid] = g_invC[gb]; bCl[tid] = g_cls[gb];
        rA0[tid] = 0.f; rA1[tid] = 0.f; rA2[tid] = 0.f;
        tB0[tid] = 0.f; tB1[tid] = 0.f; tB2[tid] = 0.f;
    }
    for (int i = tid; i < C * BN; i += 256) {
        int c = i >> 7, b = i & 127;
        projB[c][b] = g_proj[(size_t)(bBase + b) * C + c];
        projA[c][b] = g_proj[(size_t)(aBase + b) * C + c];
    }

    int tx = tid & 15, ty = tid >> 4;

    ull acc[8][4];
    #pragma unroll
    for (int i = 0; i < 8; i++)
        #pragma unroll
        for (int j = 0; j < 4; j++) acc[i][j] = 0ull;

    for (int kb = 0; kb < D; kb += BK) {
        __syncthreads();
        #pragma unroll
        for (int m = 0; m < 4; m++) {
            int lid = tid + m * 256;
            int row = lid >> 3;     // 0..127
            int quad = lid & 7;     // k offset quad*4
            float4 va = *(const float4*)&pred[(size_t)(aBase + row) * D + kb + quad * 4];
            As[quad * 4 + 0][row] = va.x; As[quad * 4 + 1][row] = va.y;
            As[quad * 4 + 2][row] = va.z; As[quad * 4 + 3][row] = va.w;
            float4 vb = *(const float4*)&pred[(size_t)(bBase + row) * D + kb + quad * 4];
            Bs[quad * 4 + 0][row] = vb.x; Bs[quad * 4 + 1][row] = vb.y;
            Bs[quad * 4 + 2][row] = vb.z; Bs[quad * 4 + 3][row] = vb.w;
        }
        __syncthreads();
        #pragma unroll
        for (int k = 0; k < BK; k++) {
            float4 a0 = *(const float4*)&As[k][ty * 4];
            float4 a1 = *(const float4*)&As[k][ty * 4 + 64];
            ulonglong2 b0 = *(const ulonglong2*)&Bs[k][tx * 4];
            ulonglong2 b1 = *(const ulonglong2*)&Bs[k][tx * 4 + 64];
            ull ap[8] = {pack2(a0.x, a0.x), pack2(a0.y, a0.y),
                         pack2(a0.z, a0.z), pack2(a0.w, a0.w),
                         pack2(a1.x, a1.x), pack2(a1.y, a1.y),
                         pack2(a1.z, a1.z), pack2(a1.w, a1.w)};
            ull bp[4] = {b0.x, b0.y, b1.x, b1.y};
            #pragma unroll
            for (int i = 0; i < 8; i++)
                #pragma unroll
                for (int j = 0; j < 4; j++)
                    fma2(acc[i][j], ap[i], bp[j]);
        }
    }

    // -------- epilogue: both pair directions from one triangular tile --------
    float t0[8], t1[8], t2[8];
    #pragma unroll
    for (int j = 0; j < 8; j++) { t0[j] = 0.f; t1[j] = 0.f; t2[j] = 0.f; }

    #pragma unroll
    for (int i = 0; i < 8; i++) {
        int r = ty * 4 + (i & 3) + (i >> 2) * 64;
        int   ca  = aCl[r];
        float pa  = aP[r], iw = aIW[r], ica = aIC[r], sqa = aSq[r];
        float sA0 = 0.f, sA1 = 0.f, sA2 = 0.f;
        #pragma unroll
        for (int j2 = 0; j2 < 4; j2++) {
            float2 gg = unpack2(acc[i][j2]);
            int cbase = tx * 4 + (j2 & 1) * 2 + (j2 >> 1) * 64;
            #pragma unroll
            for (int h = 0; h < 2; h++) {
                int c = cbase + h;
                float g  = h ? gg.y : gg.x;
                float d2 = fmaxf(sqa + bSq[c] - 2.0f * g, 0.0f) + 1e-16f;
                float invdn = rsqrtf(d2);
                int cb = bCl[c];
                if (cb != ca) {
                    float w = ica * bIC[c];
                    // direction (a -> b): class ca
                    float MA = (pa - projB[ca][c]) * iw * invdn;
                    sA0 += w; sA1 = fmaf(w, MA, sA1); sA2 = fmaf(w * MA, MA, sA2);
                    if (offd) {
                        // direction (b -> a): class cb
                        float MB = (bP[c] - projA[cb][r]) * bIW[c] * invdn;
                        int j = j2 * 2 + h;
                        t0[j] += w; t1[j] = fmaf(w, MB, t1[j]); t2[j] = fmaf(w * MB, MB, t2[j]);
                    }
                }
            }
        }
        atomicAdd(&rA0[r], sA0); atomicAdd(&rA1[r], sA1); atomicAdd(&rA2[r], sA2);
    }
    if (offd) {
        #pragma unroll
        for (int j2 = 0; j2 < 4; j2++) {
            int cbase = tx * 4 + (j2 & 1) * 2 + (j2 >> 1) * 64;
            #pragma unroll
            for (int h = 0; h < 2; h++) {
                int j = j2 * 2 + h, c = cbase + h;
                atomicAdd(&tB0[c], t0[j]); atomicAdd(&tB1[c], t1[j]); atomicAdd(&tB2[c], t2[j]);
            }
        }
    }
    __syncthreads();

    if (tid < BM) {
        int ca = aCl[tid];
        atomicAdd(&sacc[ca * 3 + 0], (double)rA0[tid]);
        atomicAdd(&sacc[ca * 3 + 1], (double)rA1[tid]);
        atomicAdd(&sacc[ca * 3 + 2], (double)rA2[tid]);
    } else if (offd) {
        int c = tid - BM;
        int cb = bCl[c];
        atomicAdd(&sacc[cb * 3 + 0], (double)tB0[c]);
        atomicAdd(&sacc[cb * 3 + 1], (double)tB1[c]);
        atomicAdd(&sacc[cb * 3 + 2], (double)tB2[c]);
    }
    __syncthreads();
    if (tid < 30) atomicAdd(&g_Sacc[tid], sacc[tid]);

    // -------- fused finalize: last CTA computes the two scalars --------
    __threadfence();
    __syncthreads();
    if (tid == 0) {
        unsigned int old = atomicAdd(&g_done, 1u);
        if (old == gridDim.x - 1) {
            __threadfence();
            double e   = (double)g_exist;
            double inv = 1.0 / (e - 1.0);
            double l1 = 0.0, l2 = 0.0;
            for (int c = 0; c < C; c++) {
                if (g_counts[c] > 0) {
                    double S0 = g_Sacc[c * 3 + 0];
                    double S1 = g_Sacc[c * 3 + 1];
                    double S2 = g_Sacc[c * 3 + 2];
                    l1 += (S0 - 2.0 * S1 + S2) * inv;
                    double mm = S1 * inv;
                    double mv = (S2 - 2.0 * mm * S1 + mm * mm * S0) * inv;
                    l2 += fabs(mv / mm);
                }
            }
            out[0] = (float)(l1 / e);
            out[1] = (float)(l2 / e);
            g_done = 0;   // reset for next graph replay
        }
    }
}

// ---------------- launch ----------------
extern "C" void kernel_launch(void* const* d_in, const int* in_sizes, int n_in,
                              void* d_out, int out_size)
{
    const float* pred   = (const float*)d_in[0];
    const int*   target = (const int*)d_in[1];   // JAX x64-disabled: int64 -> int32
    const float* W      = (const float*)d_in[2];
    int N = in_sizes[0] / D;                     // 4096
    int nb = N / BM;                             // 32
    int nblk = nb * (nb + 1) / 2;                // 528

    prep1<<<1, 256>>>(target, W, N);
    prep2<<<(N + 127) / 128, 128>>>(pred, target, W, N);
    pairKernel<<<nblk, 256>>>(pred, (float*)d_out, nb);
}

// round 5
// speedup vs baseline: 3.3808x; 1.0277x over previous
#include <cuda_runtime.h>
#include <math.h>

#define D 128
#define C 10
#define NMAX 4096
#define BM 128
#define BN 128
#define BK 32

typedef unsigned long long ull;

// -------- device scratch (zero-initialized; finalize self-resets) --------
__device__ double g_Sacc[32];
__device__ int    g_counts[C];
__device__ float  g_sq[NMAX];
__device__ float  g_proj[NMAX * C];
__device__ int    g_cls[NMAX];
__device__ float  g_pcl[NMAX];         // proj[r][cls[r]]
__device__ float  g_invwnCls[NMAX];    // 1/wn[cls[r]]
__device__ unsigned int g_done = 0;

__device__ __forceinline__ int clampC(int v) { return v < 0 ? 0 : (v >= C ? C - 1 : v); }

__device__ __forceinline__ ull pack2(float x, float y) {
    ull r; asm("mov.b64 %0, {%1,%2};" : "=l"(r) : "f"(x), "f"(y)); return r;
}
__device__ __forceinline__ void fma2(ull& d, ull a, ull b) {
    asm("fma.rn.f32x2 %0, %1, %2, %0;" : "+l"(d) : "l"(a), "l"(b));
}
__device__ __forceinline__ float2 unpack2(ull v) {
    float2 f; asm("mov.b64 {%0,%1}, %2;" : "=f"(f.x), "=f"(f.y) : "l"(v)); return f;
}
// rsqrt without MUFU: magic seed + 2 Newton steps (rel err ~4e-6)
__device__ __forceinline__ float fast_rsqrt(float x) {
    float y = __int_as_float(0x5f3759dfu - (__float_as_int(x) >> 1));
    float xh = -0.5f * x;
    y = y * fmaf(xh, y * y, 1.5f);
    y = y * fmaf(xh, y * y, 1.5f);
    return y;
}

// ---------------- prep: counts + per-row sq, proj[10], derived scalars -------
__global__ void prep(const float* __restrict__ pred,
                     const int* __restrict__ target,
                     const float* __restrict__ W, int N)
{
    __shared__ float Wsh[C][D];
    __shared__ float wnInv[C];
    __shared__ int   cnt[C];
    int tid = threadIdx.x;
    if (tid < C) cnt[tid] = 0;
    for (int i = tid; i < C * D; i += blockDim.x) Wsh[i / D][i % D] = W[i];
    __syncthreads();
    if (tid < C) {
        float s = 0.f;
        #pragma unroll 16
        for (int k = 0; k < D; k++) { float w = Wsh[tid][k]; s = fmaf(w, w, s); }
        wnInv[tid] = 1.0f / fmaxf(sqrtf(s), 1e-8f);
    }
    __syncthreads();

    int r = blockIdx.x * blockDim.x + tid;
    if (r < N) {
        int cl = clampC(target[r]);
        atomicAdd(&cnt[cl], 1);

        const float4* p4 = (const float4*)(pred + (size_t)r * D);
        float sq = 0.f;
        float proj[C];
        #pragma unroll
        for (int c = 0; c < C; c++) proj[c] = 0.f;
        #pragma unroll 4
        for (int q = 0; q < D / 4; q++) {
            float4 v = p4[q];
            float vv[4] = {v.x, v.y, v.z, v.w};
            #pragma unroll
            for (int j = 0; j < 4; j++) {
                float p = vv[j];
                int k = q * 4 + j;
                sq = fmaf(p, p, sq);
                #pragma unroll
                for (int c = 0; c < C; c++) proj[c] = fmaf(p, Wsh[c][k], proj[c]);
            }
        }
        g_sq[r]  = sq;
        g_cls[r] = cl;
        #pragma unroll
        for (int c = 0; c < C; c++) g_proj[(size_t)r * C + c] = proj[c];
        g_pcl[r]      = proj[cl];
        g_invwnCls[r] = wnInv[cl];
    }
    __syncthreads();
    if (tid < C && cnt[tid] > 0) atomicAdd(&g_counts[tid], cnt[tid]);
}

// ---------------- main: triangular fused pairwise GEMM + loss epilogue ------
__global__ __launch_bounds__(256, 2)
void pairKernel(const float* __restrict__ pred, float* __restrict__ out, int nb)
{
    __shared__ __align__(16) float As[BK][BM];
    __shared__ __align__(16) float Bs[BK][BN];
    __shared__ float projA[C][BM];
    __shared__ float projB[C][BN];
    __shared__ float icTab[C];
    __shared__ float aSq[BM], aP[BM], aIW[BM], aIC[BM];
    __shared__ float bSq[BN], bP[BN], bIW[BN], bIC[BN];
    __shared__ int   aCl[BM], bCl[BN];
    __shared__ float rA0[BM], rA1[BM], rA2[BM];
    __shared__ float tB0[BN], tB1[BN], tB2[BN];
    __shared__ double sacc[32];

    int tid = threadIdx.x;
    int idx = blockIdx.x;
    // triangular decode: row bi (<= bj)
    int bi = (int)(((float)(2 * nb + 1)
             - sqrtf((float)((2 * nb + 1) * (2 * nb + 1) - 8 * idx))) * 0.5f);
    while ((bi + 1) * nb - ((bi + 1) * bi) / 2 <= idx) bi++;
    while (bi * nb - (bi * (bi - 1)) / 2 > idx) bi--;
    int bj = bi + (idx - (bi * nb - (bi * (bi - 1)) / 2));
    int aBase = bi * BM, bBase = bj * BN;
    bool offd = (bi != bj);

    if (tid < 32) sacc[tid] = 0.0;
    if (tid < C)  icTab[tid] = 1.0f / (float)max(g_counts[tid], 1);
    if (tid < BM) {
        int ga = aBase + tid, gb = bBase + tid;
        aSq[tid] = g_sq[ga]; aP[tid] = g_pcl[ga]; aIW[tid] = g_invwnCls[ga];
        aCl[tid] = g_cls[ga];
        bSq[tid] = g_sq[gb]; bP[tid] = g_pcl[gb]; bIW[tid] = g_invwnCls[gb];
        bCl[tid] = g_cls[gb];
        rA0[tid] = 0.f; rA1[tid] = 0.f; rA2[tid] = 0.f;
        tB0[tid] = 0.f; tB1[tid] = 0.f; tB2[tid] = 0.f;
    }
    for (int i = tid; i < C * BN; i += 256) {
        int c = i >> 7, b = i & 127;
        projB[c][b] = g_proj[(size_t)(bBase + b) * C + c];
        projA[c][b] = g_proj[(size_t)(aBase + b) * C + c];
    }
    __syncthreads();
    if (tid < BM) {
        aIC[tid] = icTab[aCl[tid]];
        bIC[tid] = icTab[bCl[tid]];
    }

    int tx = tid & 15, ty = tid >> 4;

    ull acc[8][4];
    #pragma unroll
    for (int i = 0; i < 8; i++)
        #pragma unroll
        for (int j = 0; j < 4; j++) acc[i][j] = 0ull;

    for (int kb = 0; kb < D; kb += BK) {
        __syncthreads();
        #pragma unroll
        for (int m = 0; m < 4; m++) {
            int lid = tid + m * 256;
            int row = lid >> 3;     // 0..127
            int quad = lid & 7;     // k offset quad*4
            float4 va = *(const float4*)&pred[(size_t)(aBase + row) * D + kb + quad * 4];
            As[quad * 4 + 0][row] = va.x; As[quad * 4 + 1][row] = va.y;
            As[quad * 4 + 2][row] = va.z; As[quad * 4 + 3][row] = va.w;
            float4 vb = *(const float4*)&pred[(size_t)(bBase + row) * D + kb + quad * 4];
            Bs[quad * 4 + 0][row] = vb.x; Bs[quad * 4 + 1][row] = vb.y;
            Bs[quad * 4 + 2][row] = vb.z; Bs[quad * 4 + 3][row] = vb.w;
        }
        __syncthreads();
        #pragma unroll
        for (int k = 0; k < BK; k++) {
            float4 a0 = *(const float4*)&As[k][ty * 4];
            float4 a1 = *(const float4*)&As[k][ty * 4 + 64];
            ulonglong2 b0 = *(const ulonglong2*)&Bs[k][tx * 4];
            ulonglong2 b1 = *(const ulonglong2*)&Bs[k][tx * 4 + 64];
            ull ap[8] = {pack2(a0.x, a0.x), pack2(a0.y, a0.y),
                         pack2(a0.z, a0.z), pack2(a0.w, a0.w),
                         pack2(a1.x, a1.x), pack2(a1.y, a1.y),
                         pack2(a1.z, a1.z), pack2(a1.w, a1.w)};
            ull bp[4] = {b0.x, b0.y, b1.x, b1.y};
            #pragma unroll
            for (int i = 0; i < 8; i++)
                #pragma unroll
                for (int j = 0; j < 4; j++)
                    fma2(acc[i][j], ap[i], bp[j]);
        }
    }

    // -------- epilogue: both pair directions from one triangular tile --------
    float t0[8], t1[8], t2[8];
    #pragma unroll
    for (int j = 0; j < 8; j++) { t0[j] = 0.f; t1[j] = 0.f; t2[j] = 0.f; }

    #pragma unroll
    for (int i = 0; i < 8; i++) {
        int r = ty * 4 + (i & 3) + (i >> 2) * 64;
        int   ca  = aCl[r];
        float pa  = aP[r], iw = aIW[r], ica = aIC[r], sqa = aSq[r];
        float sA0 = 0.f, sA1 = 0.f, sA2 = 0.f;
        #pragma unroll
        for (int j2 = 0; j2 < 4; j2++) {
            float2 gg = unpack2(acc[i][j2]);
            int cbase = tx * 4 + (j2 & 1) * 2 + (j2 >> 1) * 64;
            #pragma unroll
            for (int h = 0; h < 2; h++) {
                int c = cbase + h;
                float g  = h ? gg.y : gg.x;
                float d2 = fmaxf(sqa + bSq[c] - 2.0f * g, 0.0f) + 1e-16f;
                float invdn = fast_rsqrt(d2);
                int cb = bCl[c];
                if (cb != ca) {
                    float w = ica * bIC[c];
                    // direction (a -> b): class ca
                    float MA = (pa - projB[ca][c]) * iw * invdn;
                    sA0 += w; sA1 = fmaf(w, MA, sA1); sA2 = fmaf(w * MA, MA, sA2);
                    if (offd) {
                        // direction (b -> a): class cb
                        float MB = (bP[c] - projA[cb][r]) * bIW[c] * invdn;
                        int j = j2 * 2 + h;
                        t0[j] += w; t1[j] = fmaf(w, MB, t1[j]); t2[j] = fmaf(w * MB, MB, t2[j]);
                    }
                }
            }
        }
        atomicAdd(&rA0[r], sA0); atomicAdd(&rA1[r], sA1); atomicAdd(&rA2[r], sA2);
    }
    if (offd) {
        #pragma unroll
        for (int j2 = 0; j2 < 4; j2++) {
            int cbase = tx * 4 + (j2 & 1) * 2 + (j2 >> 1) * 64;
            #pragma unroll
            for (int h = 0; h < 2; h++) {
                int j = j2 * 2 + h, c = cbase + h;
                atomicAdd(&tB0[c], t0[j]); atomicAdd(&tB1[c], t1[j]); atomicAdd(&tB2[c], t2[j]);
            }
        }
    }
    __syncthreads();

    if (tid < BM) {
        int ca = aCl[tid];
        atomicAdd(&sacc[ca * 3 + 0], (double)rA0[tid]);
        atomicAdd(&sacc[ca * 3 + 1], (double)rA1[tid]);
        atomicAdd(&sacc[ca * 3 + 2], (double)rA2[tid]);
    } else if (offd) {
        int c = tid - BM;
        int cb = bCl[c];
        atomicAdd(&sacc[cb * 3 + 0], (double)tB0[c]);
        atomicAdd(&sacc[cb * 3 + 1], (double)tB1[c]);
        atomicAdd(&sacc[cb * 3 + 2], (double)tB2[c]);
    }
    __syncthreads();
    if (tid < 30) atomicAdd(&g_Sacc[tid], sacc[tid]);

    // -------- fused finalize: last CTA computes scalars + resets state ------
    __threadfence();
    __syncthreads();
    if (tid == 0) {
        unsigned int old = atomicAdd(&g_done, 1u);
        if (old == gridDim.x - 1) {
            __threadfence();
            int e = 0;
            for (int c = 0; c < C; c++) e += (g_counts[c] > 0);
            double ed  = (double)e;
            double inv = 1.0 / (ed - 1.0);
            double l1 = 0.0, l2 = 0.0;
            for (int c = 0; c < C; c++) {
                if (g_counts[c] > 0) {
                    double S0 = g_Sacc[c * 3 + 0];
                    double S1 = g_Sacc[c * 3 + 1];
                    double S2 = g_Sacc[c * 3 + 2];
                    l1 += (S0 - 2.0 * S1 + S2) * inv;
                    double mm = S1 * inv;
                    double mv = (S2 - 2.0 * mm * S1 + mm * mm * S0) * inv;
                    l2 += fabs(mv / mm);
                }
            }
            out[0] = (float)(l1 / ed);
            out[1] = (float)(l2 / ed);
            // reset for next graph replay
            for (int i = 0; i < 32; i++) g_Sacc[i] = 0.0;
            for (int c = 0; c < C; c++)  g_counts[c] = 0;
            g_done = 0;
        }
    }
}

// ---------------- launch ----------------
extern "C" void kernel_launch(void* const* d_in, const int* in_sizes, int n_in,
                              void* d_out, int out_size)
{
    const float* pred   = (const float*)d_in[0];
    const int*   target = (const int*)d_in[1];   // JAX x64-disabled: int64 -> int32
    const float* W      = (const float*)d_in[2];
    int N = in_sizes[0] / D;                     // 4096
    int nb = N / BM;                             // 32
    int nblk = nb * (nb + 1) / 2;                // 528

    prep<<<(N + 127) / 128, 128>>>(pred, target, W, N);
    pairKernel<<<nblk, 256>>>(pred, (float*)d_out, nb);
}